// round 2
// baseline (speedup 1.0000x reference)
#include <cuda_runtime.h>
#include <math.h>

#define BB 64
#define NN 16384
#define CC 64
#define SLABS 32
#define NTOT (NN * CC)                 // 1,048,576 floats per sample
#define F4_PER_B (NTOT / 4)            // 262,144 float4 per sample
#define F4_PER_SLAB (F4_PER_B / SLABS) // 8,192 float4 per slab
#define F4_TOTAL ((long)BB * F4_PER_B) // 16,777,216

#define APPLY_ITERS 8
#define APPLY_THREADS 256
#define APPLY_CHUNK (APPLY_THREADS * APPLY_ITERS)        // 2048 float4 per block
#define APPLY_BLOCKS ((int)(F4_TOTAL / APPLY_CHUNK))     // 8192

// __device__ scratch (no allocations allowed)
__device__ float g_psum[BB][SLABS][CC];
__device__ float g_psq [BB][SLABS][CC];
__device__ float g_scale[BB][CC];
__device__ float g_bias [BB][CC];

// ---------------------------------------------------------------------------
// Kernel 1: partial sums / sums-of-squares per (b, slab, c)
// grid = BB*SLABS = 2048 blocks, 256 threads. Fully coalesced float4 stream,
// ascending address order (so the TAIL of x is L2-resident at kernel end).
// Each thread's float4 always covers channels [(tid&15)*4 .. +3].
// ---------------------------------------------------------------------------
__global__ __launch_bounds__(256) void stats_partial_kernel(const float* __restrict__ x) {
    const int b    = blockIdx.x / SLABS;
    const int slab = blockIdx.x % SLABS;
    const int tid  = threadIdx.x;
    const float4* __restrict__ x4 = reinterpret_cast<const float4*>(x);
    const long base = (long)b * F4_PER_B + (long)slab * F4_PER_SLAB;

    float4 s = make_float4(0.f, 0.f, 0.f, 0.f);
    float4 q = make_float4(0.f, 0.f, 0.f, 0.f);

    #pragma unroll 8
    for (int k = 0; k < F4_PER_SLAB / 256; k++) {
        float4 v = __ldg(&x4[base + (long)k * 256 + tid]);
        s.x += v.x; s.y += v.y; s.z += v.z; s.w += v.w;
        q.x = fmaf(v.x, v.x, q.x);
        q.y = fmaf(v.y, v.y, q.y);
        q.z = fmaf(v.z, v.z, q.z);
        q.w = fmaf(v.w, v.w, q.w);
    }

    __shared__ float4 ssum[256];
    __shared__ float4 ssq [256];
    ssum[tid] = s;
    ssq [tid] = q;
    __syncthreads();

    // 16 channel-quads; threads 0..15 each fold the 16 partials of quad tid
    if (tid < 16) {
        float4 S = make_float4(0.f, 0.f, 0.f, 0.f);
        float4 Q = make_float4(0.f, 0.f, 0.f, 0.f);
        #pragma unroll
        for (int m = 0; m < 16; m++) {
            float4 a = ssum[tid + 16 * m];
            float4 c = ssq [tid + 16 * m];
            S.x += a.x; S.y += a.y; S.z += a.z; S.w += a.w;
            Q.x += c.x; Q.y += c.y; Q.z += c.z; Q.w += c.w;
        }
        const int c0 = tid * 4;
        g_psum[b][slab][c0 + 0] = S.x;
        g_psum[b][slab][c0 + 1] = S.y;
        g_psum[b][slab][c0 + 2] = S.z;
        g_psum[b][slab][c0 + 3] = S.w;
        g_psq [b][slab][c0 + 0] = Q.x;
        g_psq [b][slab][c0 + 1] = Q.y;
        g_psq [b][slab][c0 + 2] = Q.z;
        g_psq [b][slab][c0 + 3] = Q.w;
    }
}

// ---------------------------------------------------------------------------
// Kernel 2: partner selection + per-(b,c) fused scale/bias.
// grid = BB blocks, CC threads.
// ---------------------------------------------------------------------------
__global__ __launch_bounds__(64) void finalize_kernel(const float* __restrict__ alpha_u,
                                                      const float* __restrict__ noise,
                                                      const int*   __restrict__ dom,
                                                      const int*   __restrict__ cls) {
    const int b = blockIdx.x;
    __shared__ int s_idx;

    if (threadIdx.x == 0) {
        const int cb = cls[b];
        const int db = dom[b];
        float best = -INFINITY;
        int bi = -1;
        #pragma unroll 1
        for (int j = 0; j < BB; j++) {
            if (cls[j] == cb && dom[j] != db) {
                float v = noise[b * BB + j];
                if (v > best) { best = v; bi = j; }  // strict > == first-max tie-break
            }
        }
        s_idx = (bi < 0) ? b : bi;
    }
    __syncthreads();
    const int idx = s_idx;
    const int c = threadIdx.x;

    float sum = 0.f, sq = 0.f, sum2 = 0.f, sq2 = 0.f;
    #pragma unroll
    for (int s = 0; s < SLABS; s++) {
        sum  += g_psum[b][s][c];
        sq   += g_psq [b][s][c];
        sum2 += g_psum[idx][s][c];
        sq2  += g_psq [idx][s][c];
    }

    const float inv_n   = 1.0f / 16384.0f;
    const float inv_nm1 = 1.0f / 16383.0f;
    const float eps = 1e-6f;

    float mu   = sum * inv_n;
    float var  = (sq  - sum  * sum  * inv_n) * inv_nm1;
    float sig  = sqrtf(var + eps);
    float mu2  = sum2 * inv_n;
    float var2 = (sq2 - sum2 * sum2 * inv_n) * inv_nm1;
    float sig2 = sqrtf(var2 + eps);

    float a = alpha_u[b] * 0.5f;   // ALPHA_MAX
    float mu_mix  = mu  * a + mu2  * (1.0f - a);
    float sig_mix = sig * a + sig2 * (1.0f - a);

    float sc = sig_mix / sig;
    g_scale[b][c] = sc;
    g_bias [b][c] = mu_mix - mu * sc;
}

// ---------------------------------------------------------------------------
// Kernel 3: out = x * scale[b][c] + bias[b][c].
// Blocks walk x in REVERSE order so the tail of x (still L2-resident from the
// stats pass) is consumed first. Streaming loads (__ldcs, no reuse after this)
// and streaming stores (__stcs, never re-read) keep L2 for x.
// Each block covers 2048 float4 inside ONE sample; every thread's channel-quad
// is fixed -> scale/bias loaded once per thread.
// ---------------------------------------------------------------------------
__global__ __launch_bounds__(APPLY_THREADS) void apply_kernel(const float* __restrict__ x,
                                                              float* __restrict__ out) {
    const float4* __restrict__ x4 = reinterpret_cast<const float4*>(x);
    float4* __restrict__ o4 = reinterpret_cast<float4*>(out);

    // reverse mapping: block 0 takes the LAST chunk
    const long base = F4_TOTAL - (long)(blockIdx.x + 1) * APPLY_CHUNK;
    const int  tid  = threadIdx.x;
    const int  b    = (int)(base >> 18);          // chunk lies inside one sample
    const int  cq   = tid & 15;                   // fixed channel-quad per thread

    const float4 s = *reinterpret_cast<const float4*>(&g_scale[b][cq * 4]);
    const float4 t = *reinterpret_cast<const float4*>(&g_bias [b][cq * 4]);

    #pragma unroll
    for (int k = 0; k < APPLY_ITERS; k++) {
        const long i4 = base + (long)k * APPLY_THREADS + tid;
        float4 v = __ldcs(&x4[i4]);
        float4 r;
        r.x = fmaf(v.x, s.x, t.x);
        r.y = fmaf(v.y, s.y, t.y);
        r.z = fmaf(v.z, s.z, t.z);
        r.w = fmaf(v.w, s.w, t.w);
        __stcs(&o4[i4], r);
    }
}

extern "C" void kernel_launch(void* const* d_in, const int* in_sizes, int n_in,
                              void* d_out, int out_size) {
    const float* x       = (const float*)d_in[0];
    const float* alpha_u = (const float*)d_in[1];
    const float* noise   = (const float*)d_in[2];
    const int*   dom     = (const int*)  d_in[3];
    const int*   cls     = (const int*)  d_in[4];
    float* out = (float*)d_out;

    stats_partial_kernel<<<BB * SLABS, 256>>>(x);
    finalize_kernel<<<BB, CC>>>(alpha_u, noise, dom, cls);
    apply_kernel<<<APPLY_BLOCKS, APPLY_THREADS>>>(x, out);
}

// round 3
// speedup vs baseline: 1.0019x; 1.0019x over previous
#include <cuda_runtime.h>
#include <math.h>

#define BB 64
#define NN 16384
#define CC 64
#define SLABS 32
#define NTOT (NN * CC)                 // 1,048,576 floats per sample
#define F4_PER_B (NTOT / 4)            // 262,144 float4 per sample
#define F4_PER_SLAB (F4_PER_B / SLABS) // 8,192 float4 per slab
#define F4_TOTAL ((long)BB * F4_PER_B) // 16,777,216

#define APPLY_ITERS 8
#define APPLY_THREADS 256
#define APPLY_CHUNK (APPLY_THREADS * APPLY_ITERS)        // 2048 float4 per block
#define APPLY_BLOCKS ((int)(F4_TOTAL / APPLY_CHUNK))     // 8192

// __device__ scratch (no allocations allowed)
__device__ float g_psum[BB][SLABS][CC];
__device__ float g_psq [BB][SLABS][CC];
__device__ float g_scale[BB][CC];
__device__ float g_bias [BB][CC];

// ---------------------------------------------------------------------------
// Kernel 1: partial sums / sums-of-squares per (b, slab, c)
// grid = BB*SLABS = 2048 blocks, 256 threads. Fully coalesced float4 stream,
// ascending address order (so the TAIL of x is L2-resident at kernel end).
// Each thread's float4 always covers channels [(tid&15)*4 .. +3].
// ---------------------------------------------------------------------------
__global__ __launch_bounds__(256) void stats_partial_kernel(const float* __restrict__ x) {
    const int b    = blockIdx.x / SLABS;
    const int slab = blockIdx.x % SLABS;
    const int tid  = threadIdx.x;
    const float4* __restrict__ x4 = reinterpret_cast<const float4*>(x);
    const long base = (long)b * F4_PER_B + (long)slab * F4_PER_SLAB;

    float4 s = make_float4(0.f, 0.f, 0.f, 0.f);
    float4 q = make_float4(0.f, 0.f, 0.f, 0.f);

    #pragma unroll 8
    for (int k = 0; k < F4_PER_SLAB / 256; k++) {
        float4 v = __ldg(&x4[base + (long)k * 256 + tid]);
        s.x += v.x; s.y += v.y; s.z += v.z; s.w += v.w;
        q.x = fmaf(v.x, v.x, q.x);
        q.y = fmaf(v.y, v.y, q.y);
        q.z = fmaf(v.z, v.z, q.z);
        q.w = fmaf(v.w, v.w, q.w);
    }

    __shared__ float4 ssum[256];
    __shared__ float4 ssq [256];
    ssum[tid] = s;
    ssq [tid] = q;
    __syncthreads();

    // 16 channel-quads; threads 0..15 each fold the 16 partials of quad tid
    if (tid < 16) {
        float4 S = make_float4(0.f, 0.f, 0.f, 0.f);
        float4 Q = make_float4(0.f, 0.f, 0.f, 0.f);
        #pragma unroll
        for (int m = 0; m < 16; m++) {
            float4 a = ssum[tid + 16 * m];
            float4 c = ssq [tid + 16 * m];
            S.x += a.x; S.y += a.y; S.z += a.z; S.w += a.w;
            Q.x += c.x; Q.y += c.y; Q.z += c.z; Q.w += c.w;
        }
        const int c0 = tid * 4;
        g_psum[b][slab][c0 + 0] = S.x;
        g_psum[b][slab][c0 + 1] = S.y;
        g_psum[b][slab][c0 + 2] = S.z;
        g_psum[b][slab][c0 + 3] = S.w;
        g_psq [b][slab][c0 + 0] = Q.x;
        g_psq [b][slab][c0 + 1] = Q.y;
        g_psq [b][slab][c0 + 2] = Q.z;
        g_psq [b][slab][c0 + 3] = Q.w;
    }
}

// ---------------------------------------------------------------------------
// Kernel 2: partner selection + per-(b,c) fused scale/bias.
// grid = BB blocks, CC threads.
// ---------------------------------------------------------------------------
__global__ __launch_bounds__(64) void finalize_kernel(const float* __restrict__ alpha_u,
                                                      const float* __restrict__ noise,
                                                      const int*   __restrict__ dom,
                                                      const int*   __restrict__ cls) {
    const int b = blockIdx.x;
    __shared__ int s_idx;

    if (threadIdx.x == 0) {
        const int cb = cls[b];
        const int db = dom[b];
        float best = -INFINITY;
        int bi = -1;
        #pragma unroll 1
        for (int j = 0; j < BB; j++) {
            if (cls[j] == cb && dom[j] != db) {
                float v = noise[b * BB + j];
                if (v > best) { best = v; bi = j; }  // strict > == first-max tie-break
            }
        }
        s_idx = (bi < 0) ? b : bi;
    }
    __syncthreads();
    const int idx = s_idx;
    const int c = threadIdx.x;

    float sum = 0.f, sq = 0.f, sum2 = 0.f, sq2 = 0.f;
    #pragma unroll
    for (int s = 0; s < SLABS; s++) {
        sum  += g_psum[b][s][c];
        sq   += g_psq [b][s][c];
        sum2 += g_psum[idx][s][c];
        sq2  += g_psq [idx][s][c];
    }

    const float inv_n   = 1.0f / 16384.0f;
    const float inv_nm1 = 1.0f / 16383.0f;
    const float eps = 1e-6f;

    float mu   = sum * inv_n;
    float var  = (sq  - sum  * sum  * inv_n) * inv_nm1;
    float sig  = sqrtf(var + eps);
    float mu2  = sum2 * inv_n;
    float var2 = (sq2 - sum2 * sum2 * inv_n) * inv_nm1;
    float sig2 = sqrtf(var2 + eps);

    float a = alpha_u[b] * 0.5f;   // ALPHA_MAX
    float mu_mix  = mu  * a + mu2  * (1.0f - a);
    float sig_mix = sig * a + sig2 * (1.0f - a);

    float sc = sig_mix / sig;
    g_scale[b][c] = sc;
    g_bias [b][c] = mu_mix - mu * sc;
}

// ---------------------------------------------------------------------------
// Kernel 3: out = x * scale[b][c] + bias[b][c].
// Blocks walk x in REVERSE order so the tail of x (still L2-resident from the
// stats pass) is consumed first. Streaming loads (__ldcs, no reuse after this)
// and streaming stores (__stcs, never re-read) keep L2 for x.
// Each block covers 2048 float4 inside ONE sample; every thread's channel-quad
// is fixed -> scale/bias loaded once per thread.
// ---------------------------------------------------------------------------
__global__ __launch_bounds__(APPLY_THREADS) void apply_kernel(const float* __restrict__ x,
                                                              float* __restrict__ out) {
    const float4* __restrict__ x4 = reinterpret_cast<const float4*>(x);
    float4* __restrict__ o4 = reinterpret_cast<float4*>(out);

    // reverse mapping: block 0 takes the LAST chunk
    const long base = F4_TOTAL - (long)(blockIdx.x + 1) * APPLY_CHUNK;
    const int  tid  = threadIdx.x;
    const int  b    = (int)(base >> 18);          // chunk lies inside one sample
    const int  cq   = tid & 15;                   // fixed channel-quad per thread

    const float4 s = *reinterpret_cast<const float4*>(&g_scale[b][cq * 4]);
    const float4 t = *reinterpret_cast<const float4*>(&g_bias [b][cq * 4]);

    #pragma unroll
    for (int k = 0; k < APPLY_ITERS; k++) {
        const long i4 = base + (long)k * APPLY_THREADS + tid;
        float4 v = __ldcs(&x4[i4]);
        float4 r;
        r.x = fmaf(v.x, s.x, t.x);
        r.y = fmaf(v.y, s.y, t.y);
        r.z = fmaf(v.z, s.z, t.z);
        r.w = fmaf(v.w, s.w, t.w);
        __stcs(&o4[i4], r);
    }
}

extern "C" void kernel_launch(void* const* d_in, const int* in_sizes, int n_in,
                              void* d_out, int out_size) {
    const float* x       = (const float*)d_in[0];
    const float* alpha_u = (const float*)d_in[1];
    const float* noise   = (const float*)d_in[2];
    const int*   dom     = (const int*)  d_in[3];
    const int*   cls     = (const int*)  d_in[4];
    float* out = (float*)d_out;

    stats_partial_kernel<<<BB * SLABS, 256>>>(x);
    finalize_kernel<<<BB, CC>>>(alpha_u, noise, dom, cls);
    apply_kernel<<<APPLY_BLOCKS, APPLY_THREADS>>>(x, out);
}